// round 1
// baseline (speedup 1.0000x reference)
#include <cuda_runtime.h>
#include <math.h>

// Problem sizes (fixed by the dataset)
#define TT   8192   // tokens
#define NE   8      // experts
#define HD   2048   // hidden
#define ID   5632   // intermediate
#define NROW (TT*2) // total routed rows (top_k = 2, distinct experts)

// ---------------- scratch (static device globals; no allocation) ----------------
__device__ int   g_count[NE];
__device__ int   g_base[NE];
__device__ int   g_ctr[NE];
__device__ int   g_tok_e[TT*2];
__device__ float g_tok_w[TT*2];
__device__ int   g_row_of[TT*2];        // (t,k) -> compact row
__device__ int   g_tok_of_row[NROW];    // compact row -> token
__device__ float g_w_of_row[NROW];      // compact row -> combine weight
__device__ float g_act[(size_t)NROW*ID];  // ~369 MB
__device__ float g_y[(size_t)NROW*HD];    // ~134 MB

// ---------------- routing ----------------
__global__ void zero_meta_kernel() {
    if (threadIdx.x < NE) g_count[threadIdx.x] = 0;
}

__global__ void route_count_kernel(const float* __restrict__ logits) {
    int t = blockIdx.x * blockDim.x + threadIdx.x;
    if (t >= TT) return;
    float v[NE];
#pragma unroll
    for (int e = 0; e < NE; e++) v[e] = logits[t * NE + e];
    int i0 = 0; float m0 = v[0];
#pragma unroll
    for (int e = 1; e < NE; e++) { if (v[e] > m0) { m0 = v[e]; i0 = e; } }
    int i1 = -1; float m1 = -INFINITY;
#pragma unroll
    for (int e = 0; e < NE; e++) { if (e != i0 && v[e] > m1) { m1 = v[e]; i1 = e; } }
    // softmax over the two selected logits (m0 >= m1)
    float z = expf(m1 - m0);
    float w0 = 1.0f / (1.0f + z);
    float w1 = z * w0;
    g_tok_e[t*2+0] = i0;  g_tok_e[t*2+1] = i1;
    g_tok_w[t*2+0] = w0;  g_tok_w[t*2+1] = w1;
    atomicAdd(&g_count[i0], 1);
    atomicAdd(&g_count[i1], 1);
}

__global__ void scan_kernel() {
    int acc = 0;
    for (int e = 0; e < NE; e++) {
        g_base[e] = acc;
        acc += g_count[e];
        g_ctr[e] = 0;
    }
}

__global__ void route_scatter_kernel() {
    int t = blockIdx.x * blockDim.x + threadIdx.x;
    if (t >= TT) return;
#pragma unroll
    for (int k = 0; k < 2; k++) {
        int e = g_tok_e[t*2+k];
        int slot = atomicAdd(&g_ctr[e], 1);
        int row = g_base[e] + slot;
        g_row_of[t*2+k] = row;
        g_tok_of_row[row] = t;
        g_w_of_row[row] = g_tok_w[t*2+k];
    }
}

// ---------------- GEMM1: act = silu(X*W1^T) * (X*W3^T), gathered rows ----------------
// Tile: BM=128 rows, BN=64 cols(I), BK=16 over H. 256 threads, 8x4 per thread.
__global__ __launch_bounds__(256) void gemm1_kernel(
    const float* __restrict__ X,
    const float* __restrict__ W1,
    const float* __restrict__ W3)
{
    const int e = blockIdx.z;
    const int cnt = g_count[e];
    const int row0 = blockIdx.y * 128;
    if (row0 >= cnt) return;
    const int base = g_base[e];
    const int n0b = blockIdx.x * 64;

    __shared__ float As [16][128];
    __shared__ float Bs1[16][64];
    __shared__ float Bs3[16][64];

    const int tid = threadIdx.x;
    const int ra = tid >> 2;          // 0..63 : A row within half-tile / B row
    const int ka = (tid & 3) * 4;     // 0,4,8,12 : k offset for loads

    int r0g = row0 + ra;
    int r1g = row0 + 64 + ra;
    const int tokA0 = (r0g < cnt) ? g_tok_of_row[base + r0g] : 0;
    const int tokA1 = (r1g < cnt) ? g_tok_of_row[base + r1g] : 0;

    const float* xp0 = X  + (size_t)tokA0 * HD + ka;
    const float* xp1 = X  + (size_t)tokA1 * HD + ka;
    const float* w1p = W1 + ((size_t)e * ID + n0b + ra) * HD + ka;
    const float* w3p = W3 + ((size_t)e * ID + n0b + ra) * HD + ka;

    const int m0 = (tid >> 4) * 8;    // 0..120
    const int n0 = (tid & 15) * 4;    // 0..60

    float accg[8][4], accu[8][4];
#pragma unroll
    for (int i = 0; i < 8; i++)
#pragma unroll
        for (int j = 0; j < 4; j++) { accg[i][j] = 0.f; accu[i][j] = 0.f; }

    for (int k0 = 0; k0 < HD; k0 += 16) {
        float4 a0 = *(const float4*)(xp0 + k0);
        float4 a1 = *(const float4*)(xp1 + k0);
        float4 b1 = *(const float4*)(w1p + k0);
        float4 b3 = *(const float4*)(w3p + k0);
        __syncthreads();
        As[ka+0][ra]     = a0.x; As[ka+1][ra]     = a0.y; As[ka+2][ra]     = a0.z; As[ka+3][ra]     = a0.w;
        As[ka+0][64+ra]  = a1.x; As[ka+1][64+ra]  = a1.y; As[ka+2][64+ra]  = a1.z; As[ka+3][64+ra]  = a1.w;
        Bs1[ka+0][ra] = b1.x; Bs1[ka+1][ra] = b1.y; Bs1[ka+2][ra] = b1.z; Bs1[ka+3][ra] = b1.w;
        Bs3[ka+0][ra] = b3.x; Bs3[ka+1][ra] = b3.y; Bs3[ka+2][ra] = b3.z; Bs3[ka+3][ra] = b3.w;
        __syncthreads();
#pragma unroll
        for (int kk = 0; kk < 16; kk++) {
            float a[8], p1[4], p3[4];
#pragma unroll
            for (int i = 0; i < 8; i++) a[i] = As[kk][m0 + i];
#pragma unroll
            for (int j = 0; j < 4; j++) { p1[j] = Bs1[kk][n0 + j]; p3[j] = Bs3[kk][n0 + j]; }
#pragma unroll
            for (int i = 0; i < 8; i++)
#pragma unroll
                for (int j = 0; j < 4; j++) {
                    accg[i][j] += a[i] * p1[j];
                    accu[i][j] += a[i] * p3[j];
                }
        }
    }

#pragma unroll
    for (int i = 0; i < 8; i++) {
        int r = row0 + m0 + i;
        if (r >= cnt) continue;
        size_t orow = (size_t)(base + r) * ID + n0b + n0;
#pragma unroll
        for (int j = 0; j < 4; j++) {
            float g = accg[i][j];
            float u = accu[i][j];
            float s = g / (1.0f + __expf(-g));   // silu
            g_act[orow + j] = s * u;
        }
    }
}

// ---------------- GEMM2: y = w_row * (act * W2^T) ----------------
// Tile: BM=128 rows, BN=64 cols(H), BK=16 over I.
__global__ __launch_bounds__(256) void gemm2_kernel(const float* __restrict__ W2)
{
    const int e = blockIdx.z;
    const int cnt = g_count[e];
    const int row0 = blockIdx.y * 128;
    if (row0 >= cnt) return;
    const int base = g_base[e];
    const int n0b = blockIdx.x * 64;

    __shared__ float As[16][128];
    __shared__ float Bs[16][64];

    const int tid = threadIdx.x;
    const int ra = tid >> 2;
    const int ka = (tid & 3) * 4;

    int r0g = row0 + ra;       if (r0g >= cnt) r0g = cnt - 1;
    int r1g = row0 + 64 + ra;  if (r1g >= cnt) r1g = cnt - 1;

    const float* ap0 = g_act + (size_t)(base + r0g) * ID + ka;
    const float* ap1 = g_act + (size_t)(base + r1g) * ID + ka;
    const float* w2p = W2 + ((size_t)e * HD + n0b + ra) * ID + ka;

    const int m0 = (tid >> 4) * 8;
    const int n0 = (tid & 15) * 4;

    float acc[8][4];
#pragma unroll
    for (int i = 0; i < 8; i++)
#pragma unroll
        for (int j = 0; j < 4; j++) acc[i][j] = 0.f;

    for (int k0 = 0; k0 < ID; k0 += 16) {
        float4 a0 = *(const float4*)(ap0 + k0);
        float4 a1 = *(const float4*)(ap1 + k0);
        float4 b  = *(const float4*)(w2p + k0);
        __syncthreads();
        As[ka+0][ra]    = a0.x; As[ka+1][ra]    = a0.y; As[ka+2][ra]    = a0.z; As[ka+3][ra]    = a0.w;
        As[ka+0][64+ra] = a1.x; As[ka+1][64+ra] = a1.y; As[ka+2][64+ra] = a1.z; As[ka+3][64+ra] = a1.w;
        Bs[ka+0][ra] = b.x; Bs[ka+1][ra] = b.y; Bs[ka+2][ra] = b.z; Bs[ka+3][ra] = b.w;
        __syncthreads();
#pragma unroll
        for (int kk = 0; kk < 16; kk++) {
            float a[8], p[4];
#pragma unroll
            for (int i = 0; i < 8; i++) a[i] = As[kk][m0 + i];
#pragma unroll
            for (int j = 0; j < 4; j++) p[j] = Bs[kk][n0 + j];
#pragma unroll
            for (int i = 0; i < 8; i++)
#pragma unroll
                for (int j = 0; j < 4; j++) acc[i][j] += a[i] * p[j];
        }
    }

#pragma unroll
    for (int i = 0; i < 8; i++) {
        int r = row0 + m0 + i;
        if (r >= cnt) continue;
        float wr = g_w_of_row[base + r];
        size_t orow = (size_t)(base + r) * HD + n0b + n0;
#pragma unroll
        for (int j = 0; j < 4; j++) g_y[orow + j] = wr * acc[i][j];
    }
}

// ---------------- combine: out[t] = y[row(t,0)] + y[row(t,1)] ----------------
__global__ void combine_kernel(float* __restrict__ out)
{
    const int HV = HD / 4;
    long long idx = (long long)blockIdx.x * blockDim.x + threadIdx.x;
    if (idx >= (long long)TT * HV) return;
    int t  = (int)(idx / HV);
    int h4 = (int)(idx % HV);
    int r0 = g_row_of[t*2+0];
    int r1 = g_row_of[t*2+1];
    float4 y0 = *((const float4*)(g_y + (size_t)r0 * HD) + h4);
    float4 y1 = *((const float4*)(g_y + (size_t)r1 * HD) + h4);
    float4 o;
    o.x = y0.x + y1.x; o.y = y0.y + y1.y; o.z = y0.z + y1.z; o.w = y0.w + y1.w;
    *((float4*)(out + (size_t)t * HD) + h4) = o;
}

// ---------------- launch ----------------
extern "C" void kernel_launch(void* const* d_in, const int* in_sizes, int n_in,
                              void* d_out, int out_size)
{
    const float* hidden = (const float*)d_in[0];   // [T, H]
    const float* logits = (const float*)d_in[1];   // [T, E]
    const float* w1     = (const float*)d_in[2];   // [E, I, H]
    const float* w2     = (const float*)d_in[3];   // [E, H, I]
    const float* w3     = (const float*)d_in[4];   // [E, I, H]
    float* out = (float*)d_out;                    // [T, H]

    zero_meta_kernel<<<1, 32>>>();
    route_count_kernel<<<(TT + 255) / 256, 256>>>(logits);
    scan_kernel<<<1, 1>>>();
    route_scatter_kernel<<<(TT + 255) / 256, 256>>>();

    dim3 g1(ID / 64, (TT + 127) / 128, NE);   // 88 x 64 x 8
    gemm1_kernel<<<g1, 256>>>(hidden, w1, w3);

    dim3 g2(HD / 64, (TT + 127) / 128, NE);   // 32 x 64 x 8
    gemm2_kernel<<<g2, 256>>>(w2);

    long long nvec = (long long)TT * (HD / 4);
    combine_kernel<<<(unsigned)((nvec + 255) / 256), 256>>>(out);
}

// round 3
// speedup vs baseline: 2.6210x; 2.6210x over previous
#include <cuda_runtime.h>
#include <cstdint>
#include <math.h>

#define TT 8192
#define NE 8
#define HD 2048
#define ID 5632
#define NROW (TT*2)

// ---------------- scratch (static device globals) ----------------
__device__ int   g_count[NE];
__device__ int   g_base[NE];
__device__ int   g_ctr[NE];
__device__ int   g_tok_e[TT*2];
__device__ float g_tok_w[TT*2];
__device__ int   g_row_of[TT*2];
__device__ int   g_tok_of_row[NROW];
__device__ float g_w_of_row[NROW];
__device__ float g_xr [(size_t)TT*HD];
__device__ float g_w1r[(size_t)NE*ID*HD];
__device__ float g_w3r[(size_t)NE*ID*HD];
__device__ float g_w2r[(size_t)NE*HD*ID];
__device__ float g_act[(size_t)NROW*ID];
__device__ float g_y  [(size_t)NROW*HD];

// ---------------- helpers ----------------
__device__ __forceinline__ float tf32r(float x) {
    float y; asm("cvt.rna.tf32.f32 %0, %1;" : "=f"(y) : "f"(x)); return y;
}
__device__ __forceinline__ void cpa16(uint32_t dst, uint64_t gsrc) {
    asm volatile("cp.async.cg.shared.global [%0], [%1], 16;" :: "r"(dst), "l"(gsrc));
}
#define CPA_COMMIT() asm volatile("cp.async.commit_group;" ::: "memory")
#define CPA_WAIT(n)  asm volatile("cp.async.wait_group %0;" :: "n"(n) : "memory")

__device__ __forceinline__ uint32_t smem_u32(const void* p) {
    uint32_t a;
    asm("{ .reg .u64 t; cvta.to.shared.u64 t, %1; cvt.u32.u64 %0, t; }" : "=r"(a) : "l"(p));
    return a;
}

__device__ __forceinline__ void mma_tf32(float* c, const uint32_t* a, const uint32_t* b) {
    asm volatile(
        "mma.sync.aligned.m16n8k8.row.col.f32.tf32.tf32.f32 "
        "{%0,%1,%2,%3},{%4,%5,%6,%7},{%8,%9},{%0,%1,%2,%3};"
        : "+f"(c[0]), "+f"(c[1]), "+f"(c[2]), "+f"(c[3])
        : "r"(a[0]), "r"(a[1]), "r"(a[2]), "r"(a[3]), "r"(b[0]), "r"(b[1]));
}

// ---------------- routing ----------------
__global__ void zero_meta_kernel() { if (threadIdx.x < NE) g_count[threadIdx.x] = 0; }

__global__ void route_count_kernel(const float* __restrict__ logits) {
    int t = blockIdx.x * blockDim.x + threadIdx.x;
    if (t >= TT) return;
    float v[NE];
#pragma unroll
    for (int e = 0; e < NE; e++) v[e] = logits[t * NE + e];
    int i0 = 0; float m0 = v[0];
#pragma unroll
    for (int e = 1; e < NE; e++) if (v[e] > m0) { m0 = v[e]; i0 = e; }
    int i1 = -1; float m1 = -INFINITY;
#pragma unroll
    for (int e = 0; e < NE; e++) if (e != i0 && v[e] > m1) { m1 = v[e]; i1 = e; }
    float z = expf(m1 - m0);
    float w0 = 1.0f / (1.0f + z);
    g_tok_e[t*2+0] = i0; g_tok_e[t*2+1] = i1;
    g_tok_w[t*2+0] = w0; g_tok_w[t*2+1] = z * w0;
    atomicAdd(&g_count[i0], 1);
    atomicAdd(&g_count[i1], 1);
}

__global__ void scan_kernel() {
    int acc = 0;
    for (int e = 0; e < NE; e++) { g_base[e] = acc; acc += g_count[e]; g_ctr[e] = 0; }
}

__global__ void route_scatter_kernel() {
    int t = blockIdx.x * blockDim.x + threadIdx.x;
    if (t >= TT) return;
#pragma unroll
    for (int k = 0; k < 2; k++) {
        int e = g_tok_e[t*2+k];
        int slot = atomicAdd(&g_ctr[e], 1);
        int row = g_base[e] + slot;
        g_row_of[t*2+k] = row;
        g_tok_of_row[row] = t;
        g_w_of_row[row] = g_tok_w[t*2+k];
    }
}

// ---------------- tf32 pre-round ----------------
__global__ void round_tf32_kernel(const float4* __restrict__ in, float4* __restrict__ out, int n4) {
    int i = blockIdx.x * blockDim.x + threadIdx.x;
    if (i >= n4) return;
    float4 v = in[i];
    v.x = tf32r(v.x); v.y = tf32r(v.y); v.z = tf32r(v.z); v.w = tf32r(v.w);
    out[i] = v;
}

// ---------------- GEMM kernels ----------------
// Block 128(M) x 128(Bcols), BK=16, 8 warps (2x4), warp tile 64x32.
// smem tiles padded to stride 20 floats -> conflict-free fragment loads.
#define BK 16
#define TSTRIDE 20
#define TILE_F (128*TSTRIDE)   // floats per tile

// GEMM1: B rows 0..63 = w1 rows (gate), 64..127 = w3 rows (up), same 64 I-cols.
__global__ void __launch_bounds__(256, 2) gemm1_mma_kernel() {
    __shared__ float As[2*TILE_F];
    __shared__ float Bs[2*TILE_F];

    const int e = blockIdx.z;
    const int cnt = g_count[e];
    const int row0 = blockIdx.y * 128;
    if (row0 >= cnt) return;
    const int base = g_base[e];
    const int nI = blockIdx.x * 64;

    const int tid  = threadIdx.x;
    const int warp = tid >> 5;
    const int lane = tid & 31;
    const int wm = warp & 1;          // 0..1 : 64-row slab
    const int wn = warp >> 1;         // 0..3 : 32-col slab
    const int g  = lane >> 2;
    const int tg = lane & 3;

    // --- global load setup: thread -> row tid>>1, 32B half (tid&1) ---
    const int lrow = tid >> 1;
    const int lofs = (tid & 1) * 8;   // float offset within 16-float slice

    int gr = row0 + lrow;
    int tok = (gr < cnt) ? g_tok_of_row[base + gr] : 0;
    const uint64_t aG = (uint64_t)__cvta_generic_to_global(g_xr + (size_t)tok * HD + lofs);
    const float* bptr = (lrow < 64)
        ? g_w1r + ((size_t)e * ID + nI + lrow) * HD + lofs
        : g_w3r + ((size_t)e * ID + nI + (lrow - 64)) * HD + lofs;
    const uint64_t bG = (uint64_t)__cvta_generic_to_global(bptr);

    const uint32_t aS = smem_u32(As) + (uint32_t)(lrow * TSTRIDE + lofs) * 4;
    const uint32_t bS = smem_u32(Bs) + (uint32_t)(lrow * TSTRIDE + lofs) * 4;
    const uint32_t stageB = TILE_F * 4;

    float acc[4][4][4];
#pragma unroll
    for (int i = 0; i < 4; i++)
#pragma unroll
        for (int j = 0; j < 4; j++)
#pragma unroll
            for (int q = 0; q < 4; q++) acc[i][j][q] = 0.f;

    // prologue: stage 0
    cpa16(aS, aG); cpa16(aS + 16, aG + 16);
    cpa16(bS, bG); cpa16(bS + 16, bG + 16);
    CPA_COMMIT();

    const int NS = HD / BK;  // 128
    for (int s = 0; s < NS; s++) {
        if (s + 1 < NS) {
            uint32_t so = ((s + 1) & 1) * stageB;
            uint64_t ko = (uint64_t)(s + 1) * BK * 4;
            cpa16(aS + so, aG + ko); cpa16(aS + so + 16, aG + ko + 16);
            cpa16(bS + so, bG + ko); cpa16(bS + so + 16, bG + ko + 16);
            CPA_COMMIT();
            CPA_WAIT(1);
        } else {
            CPA_WAIT(0);
        }
        __syncthreads();

        const float* A = As + (s & 1) * TILE_F;
        const float* B = Bs + (s & 1) * TILE_F;
#pragma unroll
        for (int kk = 0; kk < BK; kk += 8) {
            uint32_t a[4][4], b[4][2];
#pragma unroll
            for (int mf = 0; mf < 4; mf++) {
                int mb = wm * 64 + mf * 16 + g;
                a[mf][0] = __float_as_uint(A[mb * TSTRIDE + kk + tg]);
                a[mf][1] = __float_as_uint(A[(mb + 8) * TSTRIDE + kk + tg]);
                a[mf][2] = __float_as_uint(A[mb * TSTRIDE + kk + tg + 4]);
                a[mf][3] = __float_as_uint(A[(mb + 8) * TSTRIDE + kk + tg + 4]);
            }
#pragma unroll
            for (int nf = 0; nf < 4; nf++) {
                int nb = wn * 32 + nf * 8 + g;
                b[nf][0] = __float_as_uint(B[nb * TSTRIDE + kk + tg]);
                b[nf][1] = __float_as_uint(B[nb * TSTRIDE + kk + tg + 4]);
            }
#pragma unroll
            for (int mf = 0; mf < 4; mf++)
#pragma unroll
                for (int nf = 0; nf < 4; nf++) mma_tf32(acc[mf][nf], a[mf], b[nf]);
        }
        __syncthreads();
    }

    // --- epilogue: up warps (wn>=2) stage accums; gate warps apply silu*up ---
    float* up_s = As;  // 128 x 64, stride 65 -> 8320 floats (fits in As: 10240)
    if (wn >= 2) {
#pragma unroll
        for (int mf = 0; mf < 4; mf++) {
#pragma unroll
            for (int nf = 0; nf < 4; nf++) {
                int r = wm * 64 + mf * 16 + g;
                int c = (wn - 2) * 32 + nf * 8 + 2 * tg;
                up_s[r * 65 + c]       = acc[mf][nf][0];
                up_s[r * 65 + c + 1]   = acc[mf][nf][1];
                up_s[(r + 8) * 65 + c]     = acc[mf][nf][2];
                up_s[(r + 8) * 65 + c + 1] = acc[mf][nf][3];
            }
        }
    }
    __syncthreads();
    if (wn < 2) {
#pragma unroll
        for (int mf = 0; mf < 4; mf++) {
#pragma unroll
            for (int nf = 0; nf < 4; nf++) {
                int r = wm * 64 + mf * 16 + g;
                int c = wn * 32 + nf * 8 + 2 * tg;
#pragma unroll
                for (int half = 0; half < 2; half++) {
                    int rr = r + half * 8;
                    int grow = row0 + rr;
                    if (grow >= cnt) continue;
                    float gv0 = acc[mf][nf][half * 2 + 0];
                    float gv1 = acc[mf][nf][half * 2 + 1];
                    float u0 = up_s[rr * 65 + c];
                    float u1 = up_s[rr * 65 + c + 1];
                    float s0 = gv0 / (1.0f + __expf(-gv0));
                    float s1 = gv1 / (1.0f + __expf(-gv1));
                    float2 o = make_float2(tf32r(s0 * u0), tf32r(s1 * u1));
                    *(float2*)(g_act + (size_t)(base + grow) * ID + nI + c) = o;
                }
            }
        }
    }
}

// GEMM2: y = w_row * (act @ w2^T). Block 128x128 over K=ID.
__global__ void __launch_bounds__(256, 2) gemm2_mma_kernel() {
    __shared__ float As[2*TILE_F];
    __shared__ float Bs[2*TILE_F];

    const int e = blockIdx.z;
    const int cnt = g_count[e];
    const int row0 = blockIdx.y * 128;
    if (row0 >= cnt) return;
    const int base = g_base[e];
    const int n0b = blockIdx.x * 128;

    const int tid  = threadIdx.x;
    const int warp = tid >> 5;
    const int lane = tid & 31;
    const int wm = warp & 1;
    const int wn = warp >> 1;
    const int g  = lane >> 2;
    const int tg = lane & 3;

    const int lrow = tid >> 1;
    const int lofs = (tid & 1) * 8;

    int gr = row0 + lrow; if (gr >= cnt) gr = cnt - 1;
    const uint64_t aG = (uint64_t)__cvta_generic_to_global(g_act + (size_t)(base + gr) * ID + lofs);
    const uint64_t bG = (uint64_t)__cvta_generic_to_global(g_w2r + ((size_t)e * HD + n0b + lrow) * ID + lofs);

    const uint32_t aS = smem_u32(As) + (uint32_t)(lrow * TSTRIDE + lofs) * 4;
    const uint32_t bS = smem_u32(Bs) + (uint32_t)(lrow * TSTRIDE + lofs) * 4;
    const uint32_t stageB = TILE_F * 4;

    float acc[4][4][4];
#pragma unroll
    for (int i = 0; i < 4; i++)
#pragma unroll
        for (int j = 0; j < 4; j++)
#pragma unroll
            for (int q = 0; q < 4; q++) acc[i][j][q] = 0.f;

    cpa16(aS, aG); cpa16(aS + 16, aG + 16);
    cpa16(bS, bG); cpa16(bS + 16, bG + 16);
    CPA_COMMIT();

    const int NS = ID / BK;  // 352
    for (int s = 0; s < NS; s++) {
        if (s + 1 < NS) {
            uint32_t so = ((s + 1) & 1) * stageB;
            uint64_t ko = (uint64_t)(s + 1) * BK * 4;
            cpa16(aS + so, aG + ko); cpa16(aS + so + 16, aG + ko + 16);
            cpa16(bS + so, bG + ko); cpa16(bS + so + 16, bG + ko + 16);
            CPA_COMMIT();
            CPA_WAIT(1);
        } else {
            CPA_WAIT(0);
        }
        __syncthreads();

        const float* A = As + (s & 1) * TILE_F;
        const float* B = Bs + (s & 1) * TILE_F;
#pragma unroll
        for (int kk = 0; kk < BK; kk += 8) {
            uint32_t a[4][4], b[4][2];
#pragma unroll
            for (int mf = 0; mf < 4; mf++) {
                int mb = wm * 64 + mf * 16 + g;
                a[mf][0] = __float_as_uint(A[mb * TSTRIDE + kk + tg]);
                a[mf][1] = __float_as_uint(A[(mb + 8) * TSTRIDE + kk + tg]);
                a[mf][2] = __float_as_uint(A[mb * TSTRIDE + kk + tg + 4]);
                a[mf][3] = __float_as_uint(A[(mb + 8) * TSTRIDE + kk + tg + 4]);
            }
#pragma unroll
            for (int nf = 0; nf < 4; nf++) {
                int nb = wn * 32 + nf * 8 + g;
                b[nf][0] = __float_as_uint(B[nb * TSTRIDE + kk + tg]);
                b[nf][1] = __float_as_uint(B[nb * TSTRIDE + kk + tg + 4]);
            }
#pragma unroll
            for (int mf = 0; mf < 4; mf++)
#pragma unroll
                for (int nf = 0; nf < 4; nf++) mma_tf32(acc[mf][nf], a[mf], b[nf]);
        }
        __syncthreads();
    }

#pragma unroll
    for (int mf = 0; mf < 4; mf++) {
#pragma unroll
        for (int nf = 0; nf < 4; nf++) {
            int r = wm * 64 + mf * 16 + g;
            int c = wn * 32 + nf * 8 + 2 * tg;
#pragma unroll
            for (int half = 0; half < 2; half++) {
                int rr = r + half * 8;
                int grow = row0 + rr;
                if (grow >= cnt) continue;
                float wr = g_w_of_row[base + grow];
                float2 o = make_float2(wr * acc[mf][nf][half * 2 + 0],
                                       wr * acc[mf][nf][half * 2 + 1]);
                *(float2*)(g_y + (size_t)(base + grow) * HD + n0b + c) = o;
            }
        }
    }
}

// ---------------- combine ----------------
__global__ void combine_kernel(float* __restrict__ out) {
    const int HV = HD / 4;
    long long idx = (long long)blockIdx.x * blockDim.x + threadIdx.x;
    if (idx >= (long long)TT * HV) return;
    int t = (int)(idx / HV);
    int h4 = (int)(idx % HV);
    int r0 = g_row_of[t*2+0];
    int r1 = g_row_of[t*2+1];
    float4 y0 = *((const float4*)(g_y + (size_t)r0 * HD) + h4);
    float4 y1 = *((const float4*)(g_y + (size_t)r1 * HD) + h4);
    float4 o;
    o.x = y0.x + y1.x; o.y = y0.y + y1.y; o.z = y0.z + y1.z; o.w = y0.w + y1.w;
    *((float4*)(out + (size_t)t * HD) + h4) = o;
}

// ---------------- launch ----------------
extern "C" void kernel_launch(void* const* d_in, const int* in_sizes, int n_in,
                              void* d_out, int out_size)
{
    const float* hidden = (const float*)d_in[0];
    const float* logits = (const float*)d_in[1];
    const float* w1 = (const float*)d_in[2];
    const float* w2 = (const float*)d_in[3];
    const float* w3 = (const float*)d_in[4];
    float* out = (float*)d_out;

    float *xr_p, *w1_p, *w2_p, *w3_p;
    cudaGetSymbolAddress((void**)&xr_p, g_xr);
    cudaGetSymbolAddress((void**)&w1_p, g_w1r);
    cudaGetSymbolAddress((void**)&w2_p, g_w2r);
    cudaGetSymbolAddress((void**)&w3_p, g_w3r);

    {
        int n4 = TT * HD / 4;
        round_tf32_kernel<<<(n4 + 255) / 256, 256>>>((const float4*)hidden, (float4*)xr_p, n4);
        int w4 = NE * ID * HD / 4;
        round_tf32_kernel<<<(w4 + 255) / 256, 256>>>((const float4*)w1, (float4*)w1_p, w4);
        round_tf32_kernel<<<(w4 + 255) / 256, 256>>>((const float4*)w3, (float4*)w3_p, w4);
        round_tf32_kernel<<<(w4 + 255) / 256, 256>>>((const float4*)w2, (float4*)w2_p, w4);
    }

    zero_meta_kernel<<<1, 32>>>();
    route_count_kernel<<<(TT + 255) / 256, 256>>>(logits);
    scan_kernel<<<1, 1>>>();
    route_scatter_kernel<<<(TT + 255) / 256, 256>>>();

    dim3 g1(ID / 64, NROW / 128, NE);    // 88 x 128 x 8 (early-exit on empty tiles)
    gemm1_mma_kernel<<<g1, 256>>>();

    dim3 g2(HD / 128, NROW / 128, NE);   // 16 x 128 x 8
    gemm2_mma_kernel<<<g2, 256>>>();

    long long nvec = (long long)TT * (HD / 4);
    combine_kernel<<<(unsigned)((nvec + 255) / 256), 256>>>(out);
}

// round 4
// speedup vs baseline: 2.6380x; 1.0065x over previous
#include <cuda_runtime.h>
#include <cstdint>
#include <math.h>

#define TT 8192
#define NE 8
#define HD 2048
#define ID 5632
#define NROW (TT*2)

// ---------------- scratch (static device globals) ----------------
__device__ int   g_count[NE];
__device__ int   g_base[NE];
__device__ int   g_ctr[NE];
__device__ int   g_tok_e[TT*2];
__device__ float g_tok_w[TT*2];
__device__ int   g_row_of[TT*2];
__device__ int   g_tok_of_row[NROW];
__device__ float g_w_of_row[NROW];
__device__ float g_xr [(size_t)TT*HD];
__device__ float g_w1r[(size_t)NE*ID*HD];
__device__ float g_w3r[(size_t)NE*ID*HD];
__device__ float g_w2r[(size_t)NE*HD*ID];
__device__ float g_act[(size_t)NROW*ID];
__device__ float g_y  [(size_t)NROW*HD];

// ---------------- helpers ----------------
__device__ __forceinline__ float tf32r(float x) {
    float y; asm("cvt.rna.tf32.f32 %0, %1;" : "=f"(y) : "f"(x)); return y;
}
__device__ __forceinline__ void cpa16(uint32_t dst, uint64_t gsrc) {
    asm volatile("cp.async.cg.shared.global [%0], [%1], 16;" :: "r"(dst), "l"(gsrc));
}
#define CPA_COMMIT() asm volatile("cp.async.commit_group;" ::: "memory")
#define CPA_WAIT(n)  asm volatile("cp.async.wait_group %0;" :: "n"(n) : "memory")

__device__ __forceinline__ uint32_t smem_u32(const void* p) {
    uint32_t a;
    asm("{ .reg .u64 t; cvta.to.shared.u64 t, %1; cvt.u32.u64 %0, t; }" : "=r"(a) : "l"(p));
    return a;
}

__device__ __forceinline__ void mma_tf32(float* c, const uint32_t* a, const uint32_t* b) {
    asm volatile(
        "mma.sync.aligned.m16n8k8.row.col.f32.tf32.tf32.f32 "
        "{%0,%1,%2,%3},{%4,%5,%6,%7},{%8,%9},{%0,%1,%2,%3};"
        : "+f"(c[0]), "+f"(c[1]), "+f"(c[2]), "+f"(c[3])
        : "r"(a[0]), "r"(a[1]), "r"(a[2]), "r"(a[3]), "r"(b[0]), "r"(b[1]));
}

// ---------------- routing ----------------
__global__ void zero_meta_kernel() { if (threadIdx.x < NE) g_count[threadIdx.x] = 0; }

__global__ void route_count_kernel(const float* __restrict__ logits) {
    int t = blockIdx.x * blockDim.x + threadIdx.x;
    if (t >= TT) return;
    float v[NE];
#pragma unroll
    for (int e = 0; e < NE; e++) v[e] = logits[t * NE + e];
    int i0 = 0; float m0 = v[0];
#pragma unroll
    for (int e = 1; e < NE; e++) if (v[e] > m0) { m0 = v[e]; i0 = e; }
    int i1 = -1; float m1 = -INFINITY;
#pragma unroll
    for (int e = 0; e < NE; e++) if (e != i0 && v[e] > m1) { m1 = v[e]; i1 = e; }
    float z = expf(m1 - m0);
    float w0 = 1.0f / (1.0f + z);
    g_tok_e[t*2+0] = i0; g_tok_e[t*2+1] = i1;
    g_tok_w[t*2+0] = w0; g_tok_w[t*2+1] = z * w0;
    atomicAdd(&g_count[i0], 1);
    atomicAdd(&g_count[i1], 1);
}

__global__ void scan_kernel() {
    int acc = 0;
    for (int e = 0; e < NE; e++) { g_base[e] = acc; acc += g_count[e]; g_ctr[e] = 0; }
}

__global__ void route_scatter_kernel() {
    int t = blockIdx.x * blockDim.x + threadIdx.x;
    if (t >= TT) return;
#pragma unroll
    for (int k = 0; k < 2; k++) {
        int e = g_tok_e[t*2+k];
        int slot = atomicAdd(&g_ctr[e], 1);
        int row = g_base[e] + slot;
        g_row_of[t*2+k] = row;
        g_tok_of_row[row] = t;
        g_w_of_row[row] = g_tok_w[t*2+k];
    }
}

// ---------------- tf32 pre-round ----------------
__global__ void round_tf32_kernel(const float4* __restrict__ in, float4* __restrict__ out, int n4) {
    int i = blockIdx.x * blockDim.x + threadIdx.x;
    if (i >= n4) return;
    float4 v = in[i];
    v.x = tf32r(v.x); v.y = tf32r(v.y); v.z = tf32r(v.z); v.w = tf32r(v.w);
    out[i] = v;
}

// ---------------- GEMM kernels ----------------
// Block 128(M) x 128(Bcols), BK=16, 8 warps (2x4), warp tile 64x32.
// 4-stage cp.async ring in dynamic smem, one __syncthreads per K-slice.
#define BK 16
#define TSTRIDE 20
#define TILE_F (128*TSTRIDE)            // floats per tile per stage (2560)
#define NSTG 4
#define GEMM_SMEM (2*NSTG*TILE_F*4)     // 81920 bytes

// GEMM1: B rows 0..63 = w1 rows (gate), 64..127 = w3 rows (up), same 64 I-cols.
__global__ void __launch_bounds__(256, 2) gemm1_mma_kernel() {
    extern __shared__ float sm[];
    float* As = sm;                     // NSTG stages
    float* Bs = sm + NSTG * TILE_F;

    const int e = blockIdx.z;
    const int cnt = g_count[e];
    const int row0 = blockIdx.y * 128;
    if (row0 >= cnt) return;
    const int base = g_base[e];
    const int nI = blockIdx.x * 64;

    const int tid  = threadIdx.x;
    const int warp = tid >> 5;
    const int lane = tid & 31;
    const int wm = warp & 1;
    const int wn = warp >> 1;
    const int g  = lane >> 2;
    const int tg = lane & 3;

    const int lrow = tid >> 1;
    const int lofs = (tid & 1) * 8;

    int gr = row0 + lrow;
    int tok = (gr < cnt) ? g_tok_of_row[base + gr] : 0;
    const uint64_t aG = (uint64_t)__cvta_generic_to_global(g_xr + (size_t)tok * HD + lofs);
    const float* bptr = (lrow < 64)
        ? g_w1r + ((size_t)e * ID + nI + lrow) * HD + lofs
        : g_w3r + ((size_t)e * ID + nI + (lrow - 64)) * HD + lofs;
    const uint64_t bG = (uint64_t)__cvta_generic_to_global(bptr);

    const uint32_t aS = smem_u32(As) + (uint32_t)(lrow * TSTRIDE + lofs) * 4;
    const uint32_t bS = smem_u32(Bs) + (uint32_t)(lrow * TSTRIDE + lofs) * 4;
    const uint32_t stageB = TILE_F * 4;

    float acc[4][4][4];
#pragma unroll
    for (int i = 0; i < 4; i++)
#pragma unroll
        for (int j = 0; j < 4; j++)
#pragma unroll
            for (int q = 0; q < 4; q++) acc[i][j][q] = 0.f;

    const int NS = HD / BK;  // 128
    // prologue: stages 0..2
#pragma unroll
    for (int p = 0; p < NSTG - 1; p++) {
        uint32_t so = p * stageB;
        uint64_t ko = (uint64_t)p * BK * 4;
        cpa16(aS + so, aG + ko); cpa16(aS + so + 16, aG + ko + 16);
        cpa16(bS + so, bG + ko); cpa16(bS + so + 16, bG + ko + 16);
        CPA_COMMIT();
    }

    for (int s = 0; s < NS; s++) {
        CPA_WAIT(NSTG - 2);            // stage s complete
        __syncthreads();
        if (s + NSTG - 1 < NS) {       // issue stage s+3
            uint32_t so = ((s + NSTG - 1) & (NSTG - 1)) * stageB;
            uint64_t ko = (uint64_t)(s + NSTG - 1) * BK * 4;
            cpa16(aS + so, aG + ko); cpa16(aS + so + 16, aG + ko + 16);
            cpa16(bS + so, bG + ko); cpa16(bS + so + 16, bG + ko + 16);
        }
        CPA_COMMIT();                  // commit (possibly empty) to keep group count aligned

        const float* A = As + (s & (NSTG - 1)) * TILE_F;
        const float* B = Bs + (s & (NSTG - 1)) * TILE_F;
#pragma unroll
        for (int kk = 0; kk < BK; kk += 8) {
            uint32_t a[4][4], b[4][2];
#pragma unroll
            for (int mf = 0; mf < 4; mf++) {
                int mb = wm * 64 + mf * 16 + g;
                a[mf][0] = __float_as_uint(A[mb * TSTRIDE + kk + tg]);
                a[mf][1] = __float_as_uint(A[(mb + 8) * TSTRIDE + kk + tg]);
                a[mf][2] = __float_as_uint(A[mb * TSTRIDE + kk + tg + 4]);
                a[mf][3] = __float_as_uint(A[(mb + 8) * TSTRIDE + kk + tg + 4]);
            }
#pragma unroll
            for (int nf = 0; nf < 4; nf++) {
                int nb = wn * 32 + nf * 8 + g;
                b[nf][0] = __float_as_uint(B[nb * TSTRIDE + kk + tg]);
                b[nf][1] = __float_as_uint(B[nb * TSTRIDE + kk + tg + 4]);
            }
#pragma unroll
            for (int mf = 0; mf < 4; mf++)
#pragma unroll
                for (int nf = 0; nf < 4; nf++) mma_tf32(acc[mf][nf], a[mf], b[nf]);
        }
    }
    __syncthreads();

    // epilogue: up warps (wn>=2) stage accums; gate warps apply silu*up
    float* up_s = sm;  // 128 x 64, stride 65 = 8320 floats (fits)
    if (wn >= 2) {
#pragma unroll
        for (int mf = 0; mf < 4; mf++) {
#pragma unroll
            for (int nf = 0; nf < 4; nf++) {
                int r = wm * 64 + mf * 16 + g;
                int c = (wn - 2) * 32 + nf * 8 + 2 * tg;
                up_s[r * 65 + c]           = acc[mf][nf][0];
                up_s[r * 65 + c + 1]       = acc[mf][nf][1];
                up_s[(r + 8) * 65 + c]     = acc[mf][nf][2];
                up_s[(r + 8) * 65 + c + 1] = acc[mf][nf][3];
            }
        }
    }
    __syncthreads();
    if (wn < 2) {
#pragma unroll
        for (int mf = 0; mf < 4; mf++) {
#pragma unroll
            for (int nf = 0; nf < 4; nf++) {
                int r = wm * 64 + mf * 16 + g;
                int c = wn * 32 + nf * 8 + 2 * tg;
#pragma unroll
                for (int half = 0; half < 2; half++) {
                    int rr = r + half * 8;
                    int grow = row0 + rr;
                    if (grow >= cnt) continue;
                    float gv0 = acc[mf][nf][half * 2 + 0];
                    float gv1 = acc[mf][nf][half * 2 + 1];
                    float u0 = up_s[rr * 65 + c];
                    float u1 = up_s[rr * 65 + c + 1];
                    float s0 = gv0 / (1.0f + __expf(-gv0));
                    float s1 = gv1 / (1.0f + __expf(-gv1));
                    float2 o = make_float2(tf32r(s0 * u0), tf32r(s1 * u1));
                    *(float2*)(g_act + (size_t)(base + grow) * ID + nI + c) = o;
                }
            }
        }
    }
}

// GEMM2: y = w_row * (act @ w2^T). Block 128x128 over K=ID.
__global__ void __launch_bounds__(256, 2) gemm2_mma_kernel() {
    extern __shared__ float sm[];
    float* As = sm;
    float* Bs = sm + NSTG * TILE_F;

    const int e = blockIdx.z;
    const int cnt = g_count[e];
    const int row0 = blockIdx.y * 128;
    if (row0 >= cnt) return;
    const int base = g_base[e];
    const int n0b = blockIdx.x * 128;

    const int tid  = threadIdx.x;
    const int warp = tid >> 5;
    const int lane = tid & 31;
    const int wm = warp & 1;
    const int wn = warp >> 1;
    const int g  = lane >> 2;
    const int tg = lane & 3;

    const int lrow = tid >> 1;
    const int lofs = (tid & 1) * 8;

    int gr = row0 + lrow; if (gr >= cnt) gr = cnt - 1;
    const uint64_t aG = (uint64_t)__cvta_generic_to_global(g_act + (size_t)(base + gr) * ID + lofs);
    const uint64_t bG = (uint64_t)__cvta_generic_to_global(g_w2r + ((size_t)e * HD + n0b + lrow) * ID + lofs);

    const uint32_t aS = smem_u32(As) + (uint32_t)(lrow * TSTRIDE + lofs) * 4;
    const uint32_t bS = smem_u32(Bs) + (uint32_t)(lrow * TSTRIDE + lofs) * 4;
    const uint32_t stageB = TILE_F * 4;

    float acc[4][4][4];
#pragma unroll
    for (int i = 0; i < 4; i++)
#pragma unroll
        for (int j = 0; j < 4; j++)
#pragma unroll
            for (int q = 0; q < 4; q++) acc[i][j][q] = 0.f;

    const int NS = ID / BK;  // 352
#pragma unroll
    for (int p = 0; p < NSTG - 1; p++) {
        uint32_t so = p * stageB;
        uint64_t ko = (uint64_t)p * BK * 4;
        cpa16(aS + so, aG + ko); cpa16(aS + so + 16, aG + ko + 16);
        cpa16(bS + so, bG + ko); cpa16(bS + so + 16, bG + ko + 16);
        CPA_COMMIT();
    }

    for (int s = 0; s < NS; s++) {
        CPA_WAIT(NSTG - 2);
        __syncthreads();
        if (s + NSTG - 1 < NS) {
            uint32_t so = ((s + NSTG - 1) & (NSTG - 1)) * stageB;
            uint64_t ko = (uint64_t)(s + NSTG - 1) * BK * 4;
            cpa16(aS + so, aG + ko); cpa16(aS + so + 16, aG + ko + 16);
            cpa16(bS + so, bG + ko); cpa16(bS + so + 16, bG + ko + 16);
        }
        CPA_COMMIT();

        const float* A = As + (s & (NSTG - 1)) * TILE_F;
        const float* B = Bs + (s & (NSTG - 1)) * TILE_F;
#pragma unroll
        for (int kk = 0; kk < BK; kk += 8) {
            uint32_t a[4][4], b[4][2];
#pragma unroll
            for (int mf = 0; mf < 4; mf++) {
                int mb = wm * 64 + mf * 16 + g;
                a[mf][0] = __float_as_uint(A[mb * TSTRIDE + kk + tg]);
                a[mf][1] = __float_as_uint(A[(mb + 8) * TSTRIDE + kk + tg]);
                a[mf][2] = __float_as_uint(A[mb * TSTRIDE + kk + tg + 4]);
                a[mf][3] = __float_as_uint(A[(mb + 8) * TSTRIDE + kk + tg + 4]);
            }
#pragma unroll
            for (int nf = 0; nf < 4; nf++) {
                int nb = wn * 32 + nf * 8 + g;
                b[nf][0] = __float_as_uint(B[nb * TSTRIDE + kk + tg]);
                b[nf][1] = __float_as_uint(B[nb * TSTRIDE + kk + tg + 4]);
            }
#pragma unroll
            for (int mf = 0; mf < 4; mf++)
#pragma unroll
                for (int nf = 0; nf < 4; nf++) mma_tf32(acc[mf][nf], a[mf], b[nf]);
        }
    }

#pragma unroll
    for (int mf = 0; mf < 4; mf++) {
#pragma unroll
        for (int nf = 0; nf < 4; nf++) {
            int r = wm * 64 + mf * 16 + g;
            int c = wn * 32 + nf * 8 + 2 * tg;
#pragma unroll
            for (int half = 0; half < 2; half++) {
                int rr = r + half * 8;
                int grow = row0 + rr;
                if (grow >= cnt) continue;
                float wr = g_w_of_row[base + grow];
                float2 o = make_float2(wr * acc[mf][nf][half * 2 + 0],
                                       wr * acc[mf][nf][half * 2 + 1]);
                *(float2*)(g_y + (size_t)(base + grow) * HD + n0b + c) = o;
            }
        }
    }
}

// ---------------- combine ----------------
__global__ void combine_kernel(float* __restrict__ out) {
    const int HV = HD / 4;
    long long idx = (long long)blockIdx.x * blockDim.x + threadIdx.x;
    if (idx >= (long long)TT * HV) return;
    int t = (int)(idx / HV);
    int h4 = (int)(idx % HV);
    int r0 = g_row_of[t*2+0];
    int r1 = g_row_of[t*2+1];
    float4 y0 = *((const float4*)(g_y + (size_t)r0 * HD) + h4);
    float4 y1 = *((const float4*)(g_y + (size_t)r1 * HD) + h4);
    float4 o;
    o.x = y0.x + y1.x; o.y = y0.y + y1.y; o.z = y0.z + y1.z; o.w = y0.w + y1.w;
    *((float4*)(out + (size_t)t * HD) + h4) = o;
}

// ---------------- launch ----------------
extern "C" void kernel_launch(void* const* d_in, const int* in_sizes, int n_in,
                              void* d_out, int out_size)
{
    const float* hidden = (const float*)d_in[0];
    const float* logits = (const float*)d_in[1];
    const float* w1 = (const float*)d_in[2];
    const float* w2 = (const float*)d_in[3];
    const float* w3 = (const float*)d_in[4];
    float* out = (float*)d_out;

    static int attr_done = 0;
    if (!attr_done) {
        cudaFuncSetAttribute(gemm1_mma_kernel, cudaFuncAttributeMaxDynamicSharedMemorySize, GEMM_SMEM);
        cudaFuncSetAttribute(gemm2_mma_kernel, cudaFuncAttributeMaxDynamicSharedMemorySize, GEMM_SMEM);
        attr_done = 1;
    }

    float *xr_p, *w1_p, *w2_p, *w3_p;
    cudaGetSymbolAddress((void**)&xr_p, g_xr);
    cudaGetSymbolAddress((void**)&w1_p, g_w1r);
    cudaGetSymbolAddress((void**)&w2_p, g_w2r);
    cudaGetSymbolAddress((void**)&w3_p, g_w3r);

    {
        int n4 = TT * HD / 4;
        round_tf32_kernel<<<(n4 + 255) / 256, 256>>>((const float4*)hidden, (float4*)xr_p, n4);
        int w4 = NE * ID * HD / 4;
        round_tf32_kernel<<<(w4 + 255) / 256, 256>>>((const float4*)w1, (float4*)w1_p, w4);
        round_tf32_kernel<<<(w4 + 255) / 256, 256>>>((const float4*)w3, (float4*)w3_p, w4);
        round_tf32_kernel<<<(w4 + 255) / 256, 256>>>((const float4*)w2, (float4*)w2_p, w4);
    }

    zero_meta_kernel<<<1, 32>>>();
    route_count_kernel<<<(TT + 255) / 256, 256>>>(logits);
    scan_kernel<<<1, 1>>>();
    route_scatter_kernel<<<(TT + 255) / 256, 256>>>();

    dim3 g1(ID / 64, NROW / 128, NE);
    gemm1_mma_kernel<<<g1, 256, GEMM_SMEM>>>();

    dim3 g2(HD / 128, NROW / 128, NE);
    gemm2_mma_kernel<<<g2, 256, GEMM_SMEM>>>();

    long long nvec = (long long)TT * (HD / 4);
    combine_kernel<<<(unsigned)((nvec + 255) / 256), 256>>>(out);
}

// round 5
// speedup vs baseline: 4.8287x; 1.8304x over previous
#include <cuda_runtime.h>
#include <cuda_fp16.h>
#include <cstdint>
#include <math.h>

#define TT 8192
#define NE 8
#define HD 2048
#define ID 5632
#define NROW (TT*2)

// ---------------- scratch (static device globals) ----------------
__device__ int    g_count[NE];
__device__ int    g_base[NE];
__device__ int    g_ctr[NE];
__device__ int    g_tok_e[TT*2];
__device__ float  g_tok_w[TT*2];
__device__ int    g_row_of[TT*2];
__device__ int    g_tok_of_row[NROW];
__device__ float  g_w_of_row[NROW];
__device__ __half g_xh [(size_t)TT*HD];
__device__ __half g_w1h[(size_t)NE*ID*HD];
__device__ __half g_w3h[(size_t)NE*ID*HD];
__device__ __half g_w2h[(size_t)NE*HD*ID];
__device__ __half g_act[(size_t)NROW*ID];
__device__ float  g_y  [(size_t)NROW*HD];

// ---------------- helpers ----------------
__device__ __forceinline__ void cpa16(uint32_t dst, uint64_t gsrc) {
    asm volatile("cp.async.cg.shared.global [%0], [%1], 16;" :: "r"(dst), "l"(gsrc));
}
#define CPA_COMMIT() asm volatile("cp.async.commit_group;" ::: "memory")
#define CPA_WAIT(n)  asm volatile("cp.async.wait_group %0;" :: "n"(n) : "memory")

__device__ __forceinline__ uint32_t smem_u32(const void* p) {
    uint32_t a;
    asm("{ .reg .u64 t; cvta.to.shared.u64 t, %1; cvt.u32.u64 %0, t; }" : "=r"(a) : "l"(p));
    return a;
}

__device__ __forceinline__ void mma_f16(float* c, const uint32_t* a, const uint32_t* b) {
    asm volatile(
        "mma.sync.aligned.m16n8k16.row.col.f32.f16.f16.f32 "
        "{%0,%1,%2,%3},{%4,%5,%6,%7},{%8,%9},{%0,%1,%2,%3};"
        : "+f"(c[0]), "+f"(c[1]), "+f"(c[2]), "+f"(c[3])
        : "r"(a[0]), "r"(a[1]), "r"(a[2]), "r"(a[3]), "r"(b[0]), "r"(b[1]));
}

// ---------------- routing ----------------
__global__ void zero_meta_kernel() { if (threadIdx.x < NE) g_count[threadIdx.x] = 0; }

__global__ void route_count_kernel(const float* __restrict__ logits) {
    int t = blockIdx.x * blockDim.x + threadIdx.x;
    if (t >= TT) return;
    float v[NE];
#pragma unroll
    for (int e = 0; e < NE; e++) v[e] = logits[t * NE + e];
    int i0 = 0; float m0 = v[0];
#pragma unroll
    for (int e = 1; e < NE; e++) if (v[e] > m0) { m0 = v[e]; i0 = e; }
    int i1 = -1; float m1 = -INFINITY;
#pragma unroll
    for (int e = 0; e < NE; e++) if (e != i0 && v[e] > m1) { m1 = v[e]; i1 = e; }
    float z = expf(m1 - m0);
    float w0 = 1.0f / (1.0f + z);
    g_tok_e[t*2+0] = i0; g_tok_e[t*2+1] = i1;
    g_tok_w[t*2+0] = w0; g_tok_w[t*2+1] = z * w0;
    atomicAdd(&g_count[i0], 1);
    atomicAdd(&g_count[i1], 1);
}

__global__ void scan_kernel() {
    int acc = 0;
    for (int e = 0; e < NE; e++) { g_base[e] = acc; acc += g_count[e]; g_ctr[e] = 0; }
}

__global__ void route_scatter_kernel() {
    int t = blockIdx.x * blockDim.x + threadIdx.x;
    if (t >= TT) return;
#pragma unroll
    for (int k = 0; k < 2; k++) {
        int e = g_tok_e[t*2+k];
        int slot = atomicAdd(&g_ctr[e], 1);
        int row = g_base[e] + slot;
        g_row_of[t*2+k] = row;
        g_tok_of_row[row] = t;
        g_w_of_row[row] = g_tok_w[t*2+k];
    }
}

// ---------------- fp32 -> fp16 convert ----------------
__global__ void to_half_kernel(const float4* __restrict__ in, uint2* __restrict__ out, int n4) {
    int i = blockIdx.x * blockDim.x + threadIdx.x;
    if (i >= n4) return;
    float4 v = in[i];
    __half2 h0 = __floats2half2_rn(v.x, v.y);
    __half2 h1 = __floats2half2_rn(v.z, v.w);
    uint2 o;
    o.x = *reinterpret_cast<uint32_t*>(&h0);
    o.y = *reinterpret_cast<uint32_t*>(&h1);
    out[i] = o;
}

// ---------------- GEMM kernels (fp16 m16n8k16) ----------------
// Block 128(M) x 128(Bcols), BK=32 halves (64B/row), 8 warps (2x4), warp tile 64x32.
// 4-stage cp.async ring; smem rows padded to 40 halves (word stride 20 -> conflict-free).
#define BKH  32
#define PFH  40
#define TILE_H (128*PFH)                  // halves per tile per stage (5120)
#define STG_B  (TILE_H*2)                 // 10240 bytes
#define NSTG 4
#define GEMM_SMEM (2*NSTG*STG_B)          // 81920 bytes

// GEMM1: B rows 0..63 = w1 rows (gate), 64..127 = w3 rows (up), same 64 I-cols.
__global__ void __launch_bounds__(256, 2) gemm1_mma_kernel() {
    extern __shared__ char sm[];
    char* AsB = sm;
    char* BsB = sm + NSTG * STG_B;

    const int e = blockIdx.z;
    const int cnt = g_count[e];
    const int row0 = blockIdx.y * 128;
    if (row0 >= cnt) return;
    const int base = g_base[e];
    const int nI = blockIdx.x * 64;

    const int tid  = threadIdx.x;
    const int warp = tid >> 5;
    const int lane = tid & 31;
    const int wm = warp & 1;
    const int wn = warp >> 1;
    const int g  = lane >> 2;
    const int tg = lane & 3;

    const int lrow = tid >> 1;                 // 0..127
    const int lcol = (tid & 1) * 16;           // fp16 offset (0 or 16)

    int gr = row0 + lrow;
    int tok = (gr < cnt) ? g_tok_of_row[base + gr] : 0;
    const uint64_t aG = (uint64_t)__cvta_generic_to_global(g_xh + (size_t)tok * HD + lcol);
    const __half* bptr = (lrow < 64)
        ? g_w1h + ((size_t)e * ID + nI + lrow) * HD + lcol
        : g_w3h + ((size_t)e * ID + nI + (lrow - 64)) * HD + lcol;
    const uint64_t bG = (uint64_t)__cvta_generic_to_global(bptr);

    const uint32_t aS = smem_u32(AsB) + (uint32_t)(lrow * PFH + lcol) * 2;
    const uint32_t bS = smem_u32(BsB) + (uint32_t)(lrow * PFH + lcol) * 2;

    float acc[4][4][4];
#pragma unroll
    for (int i = 0; i < 4; i++)
#pragma unroll
        for (int j = 0; j < 4; j++)
#pragma unroll
            for (int q = 0; q < 4; q++) acc[i][j][q] = 0.f;

    const int NS = HD / BKH;  // 64
#pragma unroll
    for (int p = 0; p < NSTG - 1; p++) {
        uint32_t so = p * STG_B;
        uint64_t ko = (uint64_t)p * BKH * 2;
        cpa16(aS + so, aG + ko); cpa16(aS + so + 16, aG + ko + 16);
        cpa16(bS + so, bG + ko); cpa16(bS + so + 16, bG + ko + 16);
        CPA_COMMIT();
    }

    for (int s = 0; s < NS; s++) {
        CPA_WAIT(NSTG - 2);
        __syncthreads();
        if (s + NSTG - 1 < NS) {
            uint32_t so = ((s + NSTG - 1) & (NSTG - 1)) * STG_B;
            uint64_t ko = (uint64_t)(s + NSTG - 1) * BKH * 2;
            cpa16(aS + so, aG + ko); cpa16(aS + so + 16, aG + ko + 16);
            cpa16(bS + so, bG + ko); cpa16(bS + so + 16, bG + ko + 16);
        }
        CPA_COMMIT();

        const uint32_t* A = (const uint32_t*)(AsB + (s & (NSTG - 1)) * STG_B);
        const uint32_t* B = (const uint32_t*)(BsB + (s & (NSTG - 1)) * STG_B);
#pragma unroll
        for (int kc = 0; kc < 2; kc++) {          // two k16 chunks
            uint32_t a[4][4], b[4][2];
            const int kb = kc * 8;                // word offset
#pragma unroll
            for (int mf = 0; mf < 4; mf++) {
                int mb = wm * 64 + mf * 16 + g;
                a[mf][0] = A[mb * 20 + kb + tg];
                a[mf][1] = A[(mb + 8) * 20 + kb + tg];
                a[mf][2] = A[mb * 20 + kb + tg + 4];
                a[mf][3] = A[(mb + 8) * 20 + kb + tg + 4];
            }
#pragma unroll
            for (int nf = 0; nf < 4; nf++) {
                int nb = wn * 32 + nf * 8 + g;
                b[nf][0] = B[nb * 20 + kb + tg];
                b[nf][1] = B[nb * 20 + kb + tg + 4];
            }
#pragma unroll
            for (int mf = 0; mf < 4; mf++)
#pragma unroll
                for (int nf = 0; nf < 4; nf++) mma_f16(acc[mf][nf], a[mf], b[nf]);
        }
    }
    __syncthreads();

    // epilogue: up warps (wn>=2) stage accums via smem; gate warps apply silu*up
    float* up_s = (float*)sm;  // 128 x 64, stride 65 = 8320 floats (33KB, fits)
    if (wn >= 2) {
#pragma unroll
        for (int mf = 0; mf < 4; mf++) {
#pragma unroll
            for (int nf = 0; nf < 4; nf++) {
                int r = wm * 64 + mf * 16 + g;
                int c = (wn - 2) * 32 + nf * 8 + 2 * tg;
                up_s[r * 65 + c]           = acc[mf][nf][0];
                up_s[r * 65 + c + 1]       = acc[mf][nf][1];
                up_s[(r + 8) * 65 + c]     = acc[mf][nf][2];
                up_s[(r + 8) * 65 + c + 1] = acc[mf][nf][3];
            }
        }
    }
    __syncthreads();
    if (wn < 2) {
#pragma unroll
        for (int mf = 0; mf < 4; mf++) {
#pragma unroll
            for (int nf = 0; nf < 4; nf++) {
                int r = wm * 64 + mf * 16 + g;
                int c = wn * 32 + nf * 8 + 2 * tg;
#pragma unroll
                for (int half = 0; half < 2; half++) {
                    int rr = r + half * 8;
                    int grow = row0 + rr;
                    if (grow >= cnt) continue;
                    float gv0 = acc[mf][nf][half * 2 + 0];
                    float gv1 = acc[mf][nf][half * 2 + 1];
                    float u0 = up_s[rr * 65 + c];
                    float u1 = up_s[rr * 65 + c + 1];
                    float s0 = gv0 / (1.0f + __expf(-gv0));
                    float s1 = gv1 / (1.0f + __expf(-gv1));
                    __half2 h = __floats2half2_rn(s0 * u0, s1 * u1);
                    *(__half2*)(g_act + (size_t)(base + grow) * ID + nI + c) = h;
                }
            }
        }
    }
}

// GEMM2: y = w_row * (act @ w2^T). Block 128x128 over K=ID (fp16).
__global__ void __launch_bounds__(256, 2) gemm2_mma_kernel() {
    extern __shared__ char sm[];
    char* AsB = sm;
    char* BsB = sm + NSTG * STG_B;

    const int e = blockIdx.z;
    const int cnt = g_count[e];
    const int row0 = blockIdx.y * 128;
    if (row0 >= cnt) return;
    const int base = g_base[e];
    const int n0b = blockIdx.x * 128;

    const int tid  = threadIdx.x;
    const int warp = tid >> 5;
    const int lane = tid & 31;
    const int wm = warp & 1;
    const int wn = warp >> 1;
    const int g  = lane >> 2;
    const int tg = lane & 3;

    const int lrow = tid >> 1;
    const int lcol = (tid & 1) * 16;

    int gr = row0 + lrow; if (gr >= cnt) gr = cnt - 1;
    const uint64_t aG = (uint64_t)__cvta_generic_to_global(g_act + (size_t)(base + gr) * ID + lcol);
    const uint64_t bG = (uint64_t)__cvta_generic_to_global(g_w2h + ((size_t)e * HD + n0b + lrow) * ID + lcol);

    const uint32_t aS = smem_u32(AsB) + (uint32_t)(lrow * PFH + lcol) * 2;
    const uint32_t bS = smem_u32(BsB) + (uint32_t)(lrow * PFH + lcol) * 2;

    float acc[4][4][4];
#pragma unroll
    for (int i = 0; i < 4; i++)
#pragma unroll
        for (int j = 0; j < 4; j++)
#pragma unroll
            for (int q = 0; q < 4; q++) acc[i][j][q] = 0.f;

    const int NS = ID / BKH;  // 176
#pragma unroll
    for (int p = 0; p < NSTG - 1; p++) {
        uint32_t so = p * STG_B;
        uint64_t ko = (uint64_t)p * BKH * 2;
        cpa16(aS + so, aG + ko); cpa16(aS + so + 16, aG + ko + 16);
        cpa16(bS + so, bG + ko); cpa16(bS + so + 16, bG + ko + 16);
        CPA_COMMIT();
    }

    for (int s = 0; s < NS; s++) {
        CPA_WAIT(NSTG - 2);
        __syncthreads();
        if (s + NSTG - 1 < NS) {
            uint32_t so = ((s + NSTG - 1) & (NSTG - 1)) * STG_B;
            uint64_t ko = (uint64_t)(s + NSTG - 1) * BKH * 2;
            cpa16(aS + so, aG + ko); cpa16(aS + so + 16, aG + ko + 16);
            cpa16(bS + so, bG + ko); cpa16(bS + so + 16, bG + ko + 16);
        }
        CPA_COMMIT();

        const uint32_t* A = (const uint32_t*)(AsB + (s & (NSTG - 1)) * STG_B);
        const uint32_t* B = (const uint32_t*)(BsB + (s & (NSTG - 1)) * STG_B);
#pragma unroll
        for (int kc = 0; kc < 2; kc++) {
            uint32_t a[4][4], b[4][2];
            const int kb = kc * 8;
#pragma unroll
            for (int mf = 0; mf < 4; mf++) {
                int mb = wm * 64 + mf * 16 + g;
                a[mf][0] = A[mb * 20 + kb + tg];
                a[mf][1] = A[(mb + 8) * 20 + kb + tg];
                a[mf][2] = A[mb * 20 + kb + tg + 4];
                a[mf][3] = A[(mb + 8) * 20 + kb + tg + 4];
            }
#pragma unroll
            for (int nf = 0; nf < 4; nf++) {
                int nb = wn * 32 + nf * 8 + g;
                b[nf][0] = B[nb * 20 + kb + tg];
                b[nf][1] = B[nb * 20 + kb + tg + 4];
            }
#pragma unroll
            for (int mf = 0; mf < 4; mf++)
#pragma unroll
                for (int nf = 0; nf < 4; nf++) mma_f16(acc[mf][nf], a[mf], b[nf]);
        }
    }

#pragma unroll
    for (int mf = 0; mf < 4; mf++) {
#pragma unroll
        for (int nf = 0; nf < 4; nf++) {
            int r = wm * 64 + mf * 16 + g;
            int c = wn * 32 + nf * 8 + 2 * tg;
#pragma unroll
            for (int half = 0; half < 2; half++) {
                int rr = r + half * 8;
                int grow = row0 + rr;
                if (grow >= cnt) continue;
                float wr = g_w_of_row[base + grow];
                float2 o = make_float2(wr * acc[mf][nf][half * 2 + 0],
                                       wr * acc[mf][nf][half * 2 + 1]);
                *(float2*)(g_y + (size_t)(base + grow) * HD + n0b + c) = o;
            }
        }
    }
}

// ---------------- combine ----------------
__global__ void combine_kernel(float* __restrict__ out) {
    const int HV = HD / 4;
    long long idx = (long long)blockIdx.x * blockDim.x + threadIdx.x;
    if (idx >= (long long)TT * HV) return;
    int t = (int)(idx / HV);
    int h4 = (int)(idx % HV);
    int r0 = g_row_of[t*2+0];
    int r1 = g_row_of[t*2+1];
    float4 y0 = *((const float4*)(g_y + (size_t)r0 * HD) + h4);
    float4 y1 = *((const float4*)(g_y + (size_t)r1 * HD) + h4);
    float4 o;
    o.x = y0.x + y1.x; o.y = y0.y + y1.y; o.z = y0.z + y1.z; o.w = y0.w + y1.w;
    *((float4*)(out + (size_t)t * HD) + h4) = o;
}

// ---------------- launch ----------------
extern "C" void kernel_launch(void* const* d_in, const int* in_sizes, int n_in,
                              void* d_out, int out_size)
{
    const float* hidden = (const float*)d_in[0];
    const float* logits = (const float*)d_in[1];
    const float* w1 = (const float*)d_in[2];
    const float* w2 = (const float*)d_in[3];
    const float* w3 = (const float*)d_in[4];
    float* out = (float*)d_out;

    static int attr_done = 0;
    if (!attr_done) {
        cudaFuncSetAttribute(gemm1_mma_kernel, cudaFuncAttributeMaxDynamicSharedMemorySize, GEMM_SMEM);
        cudaFuncSetAttribute(gemm2_mma_kernel, cudaFuncAttributeMaxDynamicSharedMemorySize, GEMM_SMEM);
        attr_done = 1;
    }

    __half *xh_p, *w1_p, *w2_p, *w3_p;
    cudaGetSymbolAddress((void**)&xh_p, g_xh);
    cudaGetSymbolAddress((void**)&w1_p, g_w1h);
    cudaGetSymbolAddress((void**)&w2_p, g_w2h);
    cudaGetSymbolAddress((void**)&w3_p, g_w3h);

    {
        int n4 = TT * HD / 4;
        to_half_kernel<<<(n4 + 255) / 256, 256>>>((const float4*)hidden, (uint2*)xh_p, n4);
        int w4 = NE * ID * HD / 4;
        to_half_kernel<<<(w4 + 255) / 256, 256>>>((const float4*)w1, (uint2*)w1_p, w4);
        to_half_kernel<<<(w4 + 255) / 256, 256>>>((const float4*)w3, (uint2*)w3_p, w4);
        to_half_kernel<<<(w4 + 255) / 256, 256>>>((const float4*)w2, (uint2*)w2_p, w4);
    }

    zero_meta_kernel<<<1, 32>>>();
    route_count_kernel<<<(TT + 255) / 256, 256>>>(logits);
    scan_kernel<<<1, 1>>>();
    route_scatter_kernel<<<(TT + 255) / 256, 256>>>();

    dim3 g1(ID / 64, NROW / 128, NE);
    gemm1_mma_kernel<<<g1, 256, GEMM_SMEM>>>();

    dim3 g2(HD / 128, NROW / 128, NE);
    gemm2_mma_kernel<<<g2, 256, GEMM_SMEM>>>();

    long long nvec = (long long)TT * (HD / 4);
    combine_kernel<<<(unsigned)((nvec + 255) / 256), 256>>>(out);
}